// round 11
// baseline (speedup 1.0000x reference)
#include <cuda_runtime.h>
#include <math.h>

#define NUM_B 8
#define NUM_A 131072
#define NUM_C 4
#define NUM_M 64
#define BLOCK 128
#define APT 8                               // anchors per thread, CONTIGUOUS
#define GRIDX (NUM_A / (BLOCK * APT))       // 128
#define NBLOCKS (GRIDX * NUM_B)             // 1024; 7 blocks/SM -> 98.8% fill, 1 wave

// Per-block partials: [cls_sum, xy_sum, ang_sum, num_pos]. Plain stores each run.
__device__ float4 g_part[NBLOCKS];
__device__ unsigned int g_count = 0;   // self-resetting completion counter

#define ADD_F32X2(out, a, b) \
    asm("add.rn.f32x2 %0, %1, %2;" : "=l"(out) : "l"(a), "l"(b))
#define MUL_F32X2(out, a, b) \
    asm("mul.rn.f32x2 %0, %1, %2;" : "=l"(out) : "l"(a), "l"(b))
#define FMA_F32X2(out, a, b, c) \
    asm("fma.rn.f32x2 %0, %1, %2, %3;" : "=l"(out) : "l"(a), "l"(b), "l"(c))
#define PACK_F32X2(out, lo, hi) \
    asm("mov.b64 %0, {%1, %2};" : "=l"(out) : "r"(lo), "r"(hi))

__global__ __launch_bounds__(BLOCK, 8) void focal_fused_kernel(
    const float* __restrict__ cls,   // (B, A, C)
    const float* __restrict__ reg,   // (B, A, 3)
    const float* __restrict__ anc,   // (A, 3)
    const float* __restrict__ ann,   // (B, M, 4)
    float* __restrict__ out)         // (3,)
{
    // Pair-of-structs, NEGATED coords: float4 j = (-x_{2j}, -x_{2j+1}, -y_{2j}, -y_{2j+1})
    __shared__ __align__(16) float s_pair[NUM_M * 2];
    __shared__ float s_al[NUM_M];
    __shared__ float s_lb[NUM_M];

    const int b   = blockIdx.y;
    const int tid = threadIdx.x;

    if (tid < NUM_M) {
        const float* a4 = ann + ((size_t)b * NUM_M + tid) * 4;
        float x = a4[0], y = a4[1], al = a4[2], lb = a4[3];
        bool valid = (lb != -1.0f);
        // invalid -> coords pushed to -1e18: d2 ~ 1e36, never wins argmin,
        // never passes any threshold.
        const int j = tid >> 1, slot = tid & 1;
        s_pair[4 * j + slot]     = valid ? -x : -1e18f;
        s_pair[4 * j + 2 + slot] = valid ? -y : -1e18f;
        s_al[tid] = al;
        s_lb[tid] = lb;
    }
    __syncthreads();

    // 8 CONTIGUOUS anchors per thread: a = 8*th .. 8*th+7.
    const int th = blockIdx.x * BLOCK + tid;       // 0..16383 within sample

    // ---- prologue: 6 x LDG.128 of anchor coords -> packed registers ONLY ----
    unsigned long long axx[APT], ayy[APT];
    {
        float fa[24];
        const float4* p = (const float4*)(anc + (size_t)th * 24);
        #pragma unroll
        for (int i = 0; i < 6; i++) {
            float4 t = p[i];
            fa[4 * i + 0] = t.x; fa[4 * i + 1] = t.y;
            fa[4 * i + 2] = t.z; fa[4 * i + 3] = t.w;
        }
        #pragma unroll
        for (int k = 0; k < APT; k++) {
            unsigned axb = __float_as_uint(fa[3 * k + 0]);
            unsigned ayb = __float_as_uint(fa[3 * k + 1]);
            PACK_F32X2(axx[k], axb, axb);
            PACK_F32X2(ayy[k], ayb, ayb);
        }
    }   // fa dies here: hot loop carries only axx/ayy + bestkey

    // ---- 64-way argmin via bit-packed keys ----
    // (positive-float bits are u32-ordered; low 6 bits carry the annotation
    //  index; ties -> lower index, matching jnp.argmin first-index semantics)
    unsigned int bestkey[APT];
    #pragma unroll
    for (int k = 0; k < APT; k++) bestkey[k] = 0xffffffffu;
    const unsigned int KMASK = 0xffffffc0u;
    const ulonglong2* pq = (const ulonglong2*)s_pair;

    #pragma unroll 2
    for (int j = 0; j < NUM_M / 2; j++) {
        ulonglong2 q = pq[j];                 // one LDS.128 feeds all 8 anchors
        const unsigned i0 = (unsigned)(2 * j), i1 = (unsigned)(2 * j + 1);
        #pragma unroll
        for (int k = 0; k < APT; k++) {
            unsigned long long dxp, dyp, tp, d2p;
            ADD_F32X2(dxp, axx[k], q.x);      // (ax-x0, ax-x1) (coords negated)
            ADD_F32X2(dyp, ayy[k], q.y);
            MUL_F32X2(tp, dxp, dxp);
            FMA_F32X2(d2p, dyp, dyp, tp);     // == fmaf(dy,dy,dx*dx) per lane
            unsigned lo = (unsigned)d2p;
            unsigned hi = (unsigned)(d2p >> 32);
            unsigned key0 = (lo & KMASK) | i0;
            unsigned key1 = (hi & KMASK) | i1;
            bestkey[k] = min(bestkey[k], min(key0, key1));
        }
    }

    // ---- per-anchor epilogue: cold data loaded per-k (keeps regs lean) ----
    float v0 = 0.0f, v1 = 0.0f, v2 = 0.0f, v3 = 0.0f;
    #pragma unroll
    for (int k = 0; k < APT; k++) {
        const int a = th * APT + k;
        // anchor coords recovered bit-exactly from packed regs
        const float ax  = __uint_as_float((unsigned)axx[k]);
        const float ay  = __uint_as_float((unsigned)ayy[k]);
        const float aal = anc[3 * a + 2];

        const int bestm = (int)(bestkey[k] & 63u);
        const int bj = bestm >> 1, bslot = bestm & 1;
        const float bx  = -s_pair[4 * bj + bslot];
        const float by  = -s_pair[4 * bj + 2 + bslot];
        const float bal = s_al[bestm];
        const float ddx = ax - bx;
        const float ddy = ay - by;
        const float best = fmaf(ddy, ddy, ddx * ddx);   // exact winner d2
        const float dang = fabsf(aal - bal);

        // sqrt-free thresholds: dxy<20 <=> d2<400 ; dxy>=30 <=> d2>=900
        const bool positive   = (best < 400.0f) && (dang < 15.0f);
        const bool background = (best >= 900.0f) || (dang >= 22.5f);
        const bool care       = positive || background;

        if (care) {
            int label = positive ? min(max((int)s_lb[bestm], 0), NUM_C - 1) : -1;
            const float4 c4 = *(const float4*)(cls + ((size_t)b * NUM_A + a) * NUM_C);
            float cv[4] = {c4.x, c4.y, c4.z, c4.w};
            #pragma unroll
            for (int c = 0; c < NUM_C; c++) {
                float p = fminf(fmaxf(cv[c], 1e-4f), 1.0f - 1e-4f);
                bool is1 = (c == label);
                // t==1: w = 0.95*(1-p)^2, bce = -log(p)
                // t==0: w = 0.05*p^2,     bce = -log(1-p)
                float q = is1 ? (1.0f - p) : p;
                float w = (is1 ? 0.95f : 0.05f) * q * q;
                float bce = -__logf(1.0f - q);
                v0 = fmaf(w, bce, v0);
            }
        }

        if (positive) {
            const float* r3 = reg + ((size_t)b * NUM_A + a) * 3;
            float tx = bx  - ax;
            float ty = by  - ay;
            float ta = bal - aal;
            float dxr = fabsf(tx - r3[0]);
            float dyr = fabsf(ty - r3[1]);
            const float inv9 = 1.0f / 9.0f;
            float lx = (dxr <= inv9) ? (4.5f * dxr * dxr) : (dxr - 0.5f * inv9);
            float ly = (dyr <= inv9) ? (4.5f * dyr * dyr) : (dyr - 0.5f * inv9);
            v1 += lx + ly;
            v2 += fmaxf((fabsf(ta - r3[2]) - 10.0f) * 0.2f, 0.0f);
            v3 += 1.0f;
        }
    }

    // ---- block reduction: 4 quantities (4 warps) ----
    #pragma unroll
    for (int o = 16; o > 0; o >>= 1) {
        v0 += __shfl_down_sync(0xffffffffu, v0, o);
        v1 += __shfl_down_sync(0xffffffffu, v1, o);
        v2 += __shfl_down_sync(0xffffffffu, v2, o);
        v3 += __shfl_down_sync(0xffffffffu, v3, o);
    }
    __shared__ float red[BLOCK / 32][4];
    const int wid = tid >> 5, lid = tid & 31;
    if (lid == 0) {
        red[wid][0] = v0; red[wid][1] = v1; red[wid][2] = v2; red[wid][3] = v3;
    }
    __syncthreads();
    if (tid < 4) {
        float s = 0.0f;
        #pragma unroll
        for (int w = 0; w < BLOCK / 32; w++) s += red[w][tid];
        ((float*)&g_part[(size_t)b * GRIDX + blockIdx.x])[tid] = s;
        __threadfence();   // publish partials before the ticket increment
    }
    __syncthreads();

    // ---- last-block finalize (fused, no extra launches) ----
    __shared__ bool is_last;
    if (tid == 0) {
        unsigned v = atomicAdd(&g_count, 1u);
        is_last = (v == NBLOCKS - 1);
    }
    __syncthreads();
    if (!is_last) return;
    if (tid == 0) g_count = 0;   // reset for next graph replay

    // 4 warps; warp w reduces samples 2w and 2w+1 (128 partials each).
    __shared__ float s_res[NUM_B][3];
    const int w = tid >> 5, l = tid & 31;
    #pragma unroll
    for (int s = 0; s < 2; s++) {
        const int smp = 2 * w + s;
        float4 acc = make_float4(0.f, 0.f, 0.f, 0.f);
        #pragma unroll
        for (int kk = 0; kk < GRIDX / 32; kk++) {
            float4 p = g_part[(size_t)smp * GRIDX + l + 32 * kk];
            acc.x += p.x; acc.y += p.y; acc.z += p.z; acc.w += p.w;
        }
        #pragma unroll
        for (int o = 16; o > 0; o >>= 1) {
            acc.x += __shfl_down_sync(0xffffffffu, acc.x, o);
            acc.y += __shfl_down_sync(0xffffffffu, acc.y, o);
            acc.z += __shfl_down_sync(0xffffffffu, acc.z, o);
            acc.w += __shfl_down_sync(0xffffffffu, acc.w, o);
        }
        if (l == 0) {
            float denom = fmaxf(acc.w, 1.0f);
            s_res[smp][0] = acc.x / denom;
            s_res[smp][1] = acc.y / (2.0f * denom);
            s_res[smp][2] = acc.z / denom;
        }
    }
    __syncthreads();
    if (tid == 0) {
        float c = 0.f, x = 0.f, an = 0.f;
        #pragma unroll
        for (int bb = 0; bb < NUM_B; bb++) {
            c += s_res[bb][0]; x += s_res[bb][1]; an += s_res[bb][2];
        }
        out[0] = c  * (1.0f / NUM_B);
        out[1] = x  * (1.0f / NUM_B);
        out[2] = an * (1.0f / NUM_B);
    }
}

extern "C" void kernel_launch(void* const* d_in, const int* in_sizes, int n_in,
                              void* d_out, int out_size) {
    (void)in_sizes; (void)n_in; (void)out_size;
    const float* cls = (const float*)d_in[0];   // (B, A, C)
    const float* reg = (const float*)d_in[1];   // (B, A, 3)
    const float* anc = (const float*)d_in[2];   // (1, A, 3)
    const float* ann = (const float*)d_in[3];   // (B, M, 4)
    float* out = (float*)d_out;

    dim3 grid(GRIDX, NUM_B);
    focal_fused_kernel<<<grid, BLOCK>>>(cls, reg, anc, ann, out);
}

// round 13
// speedup vs baseline: 1.2486x; 1.2486x over previous
#include <cuda_runtime.h>
#include <math.h>

#define NUM_B 8
#define NUM_A 131072
#define NUM_C 4
#define NUM_M 64
#define BLOCK 256
#define APT 4                               // anchors per thread, STRIDED
#define GRIDX (NUM_A / (BLOCK * APT))       // 128
#define NBLOCKS (GRIDX * NUM_B)             // 1024
#define TPS (GRIDX * BLOCK)                 // 32768 threads per sample

// Per-block partials: [cls_sum, xy_sum, ang_sum, num_pos]. Plain stores each run.
__device__ float4 g_part[NBLOCKS];
__device__ unsigned int g_count = 0;   // self-resetting completion counter

#define ADD_F32X2(out, a, b) \
    asm("add.rn.f32x2 %0, %1, %2;" : "=l"(out) : "l"(a), "l"(b))
#define MUL_F32X2(out, a, b) \
    asm("mul.rn.f32x2 %0, %1, %2;" : "=l"(out) : "l"(a), "l"(b))
#define FMA_F32X2(out, a, b, c) \
    asm("fma.rn.f32x2 %0, %1, %2, %3;" : "=l"(out) : "l"(a), "l"(b), "l"(c))
#define PACK_F32X2(out, lo, hi) \
    asm("mov.b64 %0, {%1, %2};" : "=l"(out) : "r"(lo), "r"(hi))

__global__ __launch_bounds__(BLOCK) void focal_fused_kernel(
    const float* __restrict__ cls,   // (B, A, C)
    const float* __restrict__ reg,   // (B, A, 3)
    const float* __restrict__ anc,   // (A, 3)
    const float* __restrict__ ann,   // (B, M, 4)
    float* __restrict__ out)         // (3,)
{
    // Original-order arrays (epilogue recompute, identical to proven kernel):
    __shared__ __align__(16) float s_pair[NUM_M * 2]; // (-x0,-x1,-y0,-y1) by ORIG pair
    __shared__ float s_al[NUM_M];
    __shared__ float s_lb[NUM_M];
    // Sort machinery:
    __shared__ float s_un[NUM_M];     // unsorted search-x (+1e18 if invalid)
    __shared__ float s_sx[NUM_M];     // SORTED search-x ascending
    __shared__ float s_tnx[NUM_M];    // ranked -x
    __shared__ float s_tny[NUM_M];    // ranked -y
    __shared__ int   s_torig[NUM_M];  // ranked original index
    // Scan arrays (sorted order, pair-of-structs, padded to 64 pairs):
    __shared__ __align__(16) float4 s_sp[NUM_M];   // (-x_{2j},-x_{2j+1},-y_{2j},-y_{2j+1})
    __shared__ uint2 s_og[NUM_M];                  // orig indices of the pair

    const int b   = blockIdx.y;
    const int tid = threadIdx.x;

    float xv = 0.0f, nx = 0.0f, ny = 0.0f;
    if (tid < NUM_M) {
        const float* a4 = ann + ((size_t)b * NUM_M + tid) * 4;
        float x = a4[0], y = a4[1], al = a4[2], lb = a4[3];
        bool valid = (lb != -1.0f);
        // invalid -> +1e18 sort key (sorts last, never inside any window),
        // -1e18 coords (d2 ~ 1e36, never wins, never passes thresholds).
        const int j = tid >> 1, slot = tid & 1;
        s_pair[4 * j + slot]     = valid ? -x : -1e18f;
        s_pair[4 * j + 2 + slot] = valid ? -y : -1e18f;
        s_al[tid] = al;
        s_lb[tid] = lb;
        xv = valid ? x : 1e18f;
        nx = valid ? -x : -1e18f;
        ny = valid ? -y : -1e18f;
        s_un[tid] = xv;
    }
    __syncthreads();

    // Parallel rank-sort by x (stable: ties break by original index).
    if (tid < NUM_M) {
        int r = 0;
        #pragma unroll
        for (int j = 0; j < NUM_M; j++) {
            float xj = s_un[j];                     // broadcast read
            r += ((xj < xv) || (xj == xv && j < tid)) ? 1 : 0;
        }
        s_sx[r]    = xv;
        s_tnx[r]   = nx;
        s_tny[r]   = ny;
        s_torig[r] = tid;
    }
    __syncthreads();

    // Pack sorted pairs; pad pairs 32..63 with far-away dummies so the scan
    // loop needs no bounds predication (supersets are provably harmless).
    if (tid < NUM_M) {
        if (tid < NUM_M / 2) {
            s_sp[tid] = make_float4(s_tnx[2 * tid], s_tnx[2 * tid + 1],
                                    s_tny[2 * tid], s_tny[2 * tid + 1]);
            s_og[tid] = make_uint2((unsigned)s_torig[2 * tid],
                                   (unsigned)s_torig[2 * tid + 1]);
        } else {
            s_sp[tid] = make_float4(-1e18f, -1e18f, -1e18f, -1e18f);
            s_og[tid] = make_uint2(0u, 0u);
        }
    }
    __syncthreads();

    const int t = blockIdx.x * BLOCK + tid;   // thread index within sample
    const unsigned KMASK = 0xffffffc0u;
    float v0 = 0.0f, v1 = 0.0f, v2 = 0.0f, v3 = 0.0f;

    #pragma unroll 1
    for (int k = 0; k < APT; k++) {
        const int a = t + k * TPS;
        const float ax  = anc[3 * a + 0];
        const float ay  = anc[3 * a + 1];
        const float aal = anc[3 * a + 2];
        unsigned long long axx, ayy;
        {
            unsigned xb = __float_as_uint(ax), yb = __float_as_uint(ay);
            PACK_F32X2(axx, xb, xb);
            PACK_F32X2(ayy, yb, yb);
        }

        // Branchless lower-bound binary searches for the x-window [ax-30, ax+30).
        // Any annotation with d < 30 has |dx| < 30 => inside this window.
        const float tlo = ax - 30.0f, thi = ax + 30.0f;
        int lo = 0, hi = 0;
        #pragma unroll
        for (int s = 32; s >= 1; s >>= 1) {
            if (s_sx[lo + s - 1] < tlo) lo += s;
            if (s_sx[hi + s - 1] < thi) hi += s;
        }
        if (s_sx[lo] < tlo) lo += 1;   // final fix step: results in [0, 64]
        if (s_sx[hi] < thi) hi += 1;

        const int p0 = lo >> 1;
        int trips = ((hi + 1) >> 1) - p0;       // pairs covering [lo, hi)
        // warp-max trip count; all lanes run the same count (extra candidates
        // a lane scans are real-or-padded annotations => superset-safe).
        int nmax = trips;
        #pragma unroll
        for (int o = 16; o > 0; o >>= 1)
            nmax = max(nmax, __shfl_xor_sync(0xffffffffu, nmax, o));

        // Pruned argmin via bit-packed keys (identical semantics to full scan:
        // positive-float bits u32-ordered, low 6 bits = orig index, ties ->
        // lower original index == jnp.argmin first-index).
        unsigned bestkey = 0xffffffffu;
        const ulonglong2* sp = (const ulonglong2*)s_sp;
        for (int j = 0; j < nmax; j++) {
            ulonglong2 q = sp[p0 + j];          // (-x0,-x1), (-y0,-y1)
            uint2 og = s_og[p0 + j];
            unsigned long long dxp, dyp, tp, d2p;
            ADD_F32X2(dxp, axx, q.x);           // (ax-x0, ax-x1)
            ADD_F32X2(dyp, ayy, q.y);
            MUL_F32X2(tp, dxp, dxp);
            FMA_F32X2(d2p, dyp, dyp, tp);       // == fmaf(dy,dy,dx*dx) per lane
            unsigned klo = ((unsigned)d2p & KMASK) | og.x;
            unsigned khi = ((unsigned)(d2p >> 32) & KMASK) | og.y;
            bestkey = min(bestkey, min(klo, khi));
        }

        // ---- epilogue: recompute EXACT values from original-order arrays ----
        const int bestm = (int)(bestkey & 63u);
        const int bj = bestm >> 1, bslot = bestm & 1;
        const float bx  = -s_pair[4 * bj + bslot];
        const float by  = -s_pair[4 * bj + 2 + bslot];
        const float bal = s_al[bestm];
        const float ddx = ax - bx;
        const float ddy = ay - by;
        const float best = fmaf(ddy, ddy, ddx * ddx);
        const float dang = fabsf(aal - bal);

        // sqrt-free thresholds: dxy<20 <=> d2<400 ; dxy>=30 <=> d2>=900
        const bool positive   = (best < 400.0f) && (dang < 15.0f);
        const bool background = (best >= 900.0f) || (dang >= 22.5f);
        const bool care       = positive || background;

        if (care) {
            int label = positive ? min(max((int)s_lb[bestm], 0), NUM_C - 1) : -1;
            const float4 c4 = *(const float4*)(cls + ((size_t)b * NUM_A + a) * NUM_C);
            float cv[4] = {c4.x, c4.y, c4.z, c4.w};
            #pragma unroll
            for (int c = 0; c < NUM_C; c++) {
                float p = fminf(fmaxf(cv[c], 1e-4f), 1.0f - 1e-4f);
                bool is1 = (c == label);
                // t==1: w = 0.95*(1-p)^2, bce = -log(p)
                // t==0: w = 0.05*p^2,     bce = -log(1-p)
                float q = is1 ? (1.0f - p) : p;
                float w = (is1 ? 0.95f : 0.05f) * q * q;
                float bce = -__logf(1.0f - q);
                v0 = fmaf(w, bce, v0);
            }
        }

        if (positive) {
            const float* r3 = reg + ((size_t)b * NUM_A + a) * 3;
            float tx = bx  - ax;
            float ty = by  - ay;
            float ta = bal - aal;
            float dxr = fabsf(tx - r3[0]);
            float dyr = fabsf(ty - r3[1]);
            const float inv9 = 1.0f / 9.0f;
            float lx = (dxr <= inv9) ? (4.5f * dxr * dxr) : (dxr - 0.5f * inv9);
            float ly = (dyr <= inv9) ? (4.5f * dyr * dyr) : (dyr - 0.5f * inv9);
            v1 += lx + ly;
            v2 += fmaxf((fabsf(ta - r3[2]) - 10.0f) * 0.2f, 0.0f);
            v3 += 1.0f;
        }
    }

    // ---- block reduction: 4 quantities ----
    #pragma unroll
    for (int o = 16; o > 0; o >>= 1) {
        v0 += __shfl_down_sync(0xffffffffu, v0, o);
        v1 += __shfl_down_sync(0xffffffffu, v1, o);
        v2 += __shfl_down_sync(0xffffffffu, v2, o);
        v3 += __shfl_down_sync(0xffffffffu, v3, o);
    }
    __shared__ float red[BLOCK / 32][4];
    const int wid = tid >> 5, lid = tid & 31;
    if (lid == 0) {
        red[wid][0] = v0; red[wid][1] = v1; red[wid][2] = v2; red[wid][3] = v3;
    }
    __syncthreads();
    if (tid < 4) {
        float s = 0.0f;
        #pragma unroll
        for (int w = 0; w < BLOCK / 32; w++) s += red[w][tid];
        ((float*)&g_part[(size_t)b * GRIDX + blockIdx.x])[tid] = s;
        __threadfence();   // publish partials before the ticket increment
    }
    __syncthreads();

    // ---- last-block finalize (fused, no extra launches) ----
    __shared__ bool is_last;
    if (tid == 0) {
        unsigned v = atomicAdd(&g_count, 1u);
        is_last = (v == NBLOCKS - 1);
    }
    __syncthreads();
    if (!is_last) return;
    if (tid == 0) g_count = 0;   // reset for next graph replay

    // 8 warps: warp w reduces sample b=w over its 128 partials.
    __shared__ float s_res[NUM_B][3];
    const int w = tid >> 5, l = tid & 31;
    float4 acc = make_float4(0.f, 0.f, 0.f, 0.f);
    #pragma unroll
    for (int kk = 0; kk < GRIDX / 32; kk++) {
        float4 p = g_part[(size_t)w * GRIDX + l + 32 * kk];
        acc.x += p.x; acc.y += p.y; acc.z += p.z; acc.w += p.w;
    }
    #pragma unroll
    for (int o = 16; o > 0; o >>= 1) {
        acc.x += __shfl_down_sync(0xffffffffu, acc.x, o);
        acc.y += __shfl_down_sync(0xffffffffu, acc.y, o);
        acc.z += __shfl_down_sync(0xffffffffu, acc.z, o);
        acc.w += __shfl_down_sync(0xffffffffu, acc.w, o);
    }
    if (l == 0) {
        float denom = fmaxf(acc.w, 1.0f);
        s_res[w][0] = acc.x / denom;
        s_res[w][1] = acc.y / (2.0f * denom);
        s_res[w][2] = acc.z / denom;
    }
    __syncthreads();
    if (tid == 0) {
        float c = 0.f, x = 0.f, an = 0.f;
        #pragma unroll
        for (int bb = 0; bb < NUM_B; bb++) {
            c += s_res[bb][0]; x += s_res[bb][1]; an += s_res[bb][2];
        }
        out[0] = c  * (1.0f / NUM_B);
        out[1] = x  * (1.0f / NUM_B);
        out[2] = an * (1.0f / NUM_B);
    }
}

extern "C" void kernel_launch(void* const* d_in, const int* in_sizes, int n_in,
                              void* d_out, int out_size) {
    (void)in_sizes; (void)n_in; (void)out_size;
    const float* cls = (const float*)d_in[0];   // (B, A, C)
    const float* reg = (const float*)d_in[1];   // (B, A, 3)
    const float* anc = (const float*)d_in[2];   // (1, A, 3)
    const float* ann = (const float*)d_in[3];   // (B, M, 4)
    float* out = (float*)d_out;

    dim3 grid(GRIDX, NUM_B);
    focal_fused_kernel<<<grid, BLOCK>>>(cls, reg, anc, ann, out);
}

// round 14
// speedup vs baseline: 1.3704x; 1.0976x over previous
#include <cuda_runtime.h>
#include <math.h>

#define NUM_B 8
#define NUM_A 131072
#define NUM_C 4
#define NUM_M 64
#define BLOCK 256
#define APT 4                               // anchors per thread, STRIDED
#define GRIDX (NUM_A / (BLOCK * APT))       // 128
#define NBLOCKS (GRIDX * NUM_B)             // 1024
#define TPS (GRIDX * BLOCK)                 // 32768 threads per sample
#define NBKT 64                             // 8-px x-buckets over [0, 512)

// Per-block partials: [cls_sum, xy_sum, ang_sum, num_pos]. Plain stores each run.
__device__ float4 g_part[NBLOCKS];
__device__ unsigned int g_count = 0;   // self-resetting completion counter

#define ADD_F32X2(out, a, b) \
    asm("add.rn.f32x2 %0, %1, %2;" : "=l"(out) : "l"(a), "l"(b))
#define MUL_F32X2(out, a, b) \
    asm("mul.rn.f32x2 %0, %1, %2;" : "=l"(out) : "l"(a), "l"(b))
#define FMA_F32X2(out, a, b, c) \
    asm("fma.rn.f32x2 %0, %1, %2, %3;" : "=l"(out) : "l"(a), "l"(b), "l"(c))
#define PACK_F32X2(out, lo, hi) \
    asm("mov.b64 %0, {%1, %2};" : "=l"(out) : "r"(lo), "r"(hi))

__global__ __launch_bounds__(BLOCK) void focal_fused_kernel(
    const float* __restrict__ cls,   // (B, A, C)
    const float* __restrict__ reg,   // (B, A, 3)
    const float* __restrict__ anc,   // (A, 3)
    const float* __restrict__ ann,   // (B, M, 4)
    float* __restrict__ out)         // (3,)
{
    // Original-order arrays (exact epilogue recompute):
    __shared__ __align__(16) float s_pair[NUM_M * 2]; // (-x0,-x1,-y0,-y1) by ORIG pair
    __shared__ float s_al[NUM_M];
    __shared__ float s_lb[NUM_M];
    // Sort machinery:
    __shared__ float s_un[NUM_M];      // unsorted x (+1e18 if invalid)
    __shared__ float s_tnx[NUM_M];     // ranked -x
    __shared__ float s_tny[NUM_M];     // ranked -y
    __shared__ int   s_torig[NUM_M];   // ranked original index
    __shared__ unsigned s_lut[NBKT];   // per-bucket: lo | (hi << 8)
    // Scan pairs (sorted order): (-x_{2p}, -x_{2p+1}, -y_{2p}, -y_{2p+1})
    __shared__ __align__(16) float4 s_sp[NUM_M / 2];

    const int b   = blockIdx.y;
    const int tid = threadIdx.x;

    float xv = 0.0f, nx = 0.0f, ny = 0.0f;
    if (tid < NUM_M) {
        const float* a4 = ann + ((size_t)b * NUM_M + tid) * 4;
        float x = a4[0], y = a4[1], al = a4[2], lb = a4[3];
        bool valid = (lb != -1.0f);
        // invalid -> +1e18 sort key (sorts last, outside every bucket window),
        // -1e18 coords (d2 ~ 1e36, never wins, never passes thresholds).
        const int j = tid >> 1, slot = tid & 1;
        s_pair[4 * j + slot]     = valid ? -x : -1e18f;
        s_pair[4 * j + 2 + slot] = valid ? -y : -1e18f;
        s_al[tid] = al;
        s_lb[tid] = lb;
        xv = valid ? x : 1e18f;
        nx = valid ? -x : -1e18f;
        ny = valid ? -y : -1e18f;
        s_un[tid] = xv;
    }
    __syncthreads();

    // One fused pass (threads 0..63): rank-sort by x (stable) + bucket LUT.
    // Bucket g covers anchors with ax in [8g, 8g+8); its candidate window
    // [8g-30, 8g+38) is a superset of every such anchor's [ax-30, ax+30).
    if (tid < NUM_M) {
        const float tlo = tid * 8.0f - 30.0f;
        const float thi = tid * 8.0f + 38.0f;
        int r = 0, lo = 0, hi = 0;
        #pragma unroll
        for (int j = 0; j < NUM_M; j++) {
            float xj = s_un[j];                       // broadcast read
            r  += ((xj < xv) || (xj == xv && j < tid)) ? 1 : 0;
            lo += (xj < tlo) ? 1 : 0;
            hi += (xj < thi) ? 1 : 0;
        }
        s_tnx[r]   = nx;
        s_tny[r]   = ny;
        s_torig[r] = tid;
        s_lut[tid] = (unsigned)lo | ((unsigned)hi << 8);
    }
    __syncthreads();

    // Pack sorted pairs for the 128-bit scan.
    if (tid < NUM_M / 2) {
        s_sp[tid] = make_float4(s_tnx[2 * tid], s_tnx[2 * tid + 1],
                                s_tny[2 * tid], s_tny[2 * tid + 1]);
    }
    __syncthreads();

    const int t = blockIdx.x * BLOCK + tid;   // thread index within sample
    const unsigned KMASK = 0xffffffc0u;
    float v0 = 0.0f, v1 = 0.0f, v2 = 0.0f, v3 = 0.0f;

    #pragma unroll 1
    for (int k = 0; k < APT; k++) {
        const int a = t + k * TPS;
        const float ax  = anc[3 * a + 0];
        const float ay  = anc[3 * a + 1];
        const float aal = anc[3 * a + 2];
        unsigned long long axx, ayy;
        {
            unsigned xb = __float_as_uint(ax), yb = __float_as_uint(ay);
            PACK_F32X2(axx, xb, xb);
            PACK_F32X2(ayy, yb, yb);
        }

        // O(1) window lookup: single LDS from the bucket LUT.
        const int g = min((int)(ax * 0.125f), NBKT - 1);
        const unsigned lut = s_lut[g];
        const int lo = (int)(lut & 0xffu);
        const int hi = (int)(lut >> 8);
        const int p0 = lo >> 1;
        const int trips = ((hi + 1) >> 1) - p0;   // pairs covering [lo, hi)

        // Pruned argmin via bit-packed keys (positive-float bits u32-ordered;
        // low 6 bits carry the SORTED index; winner remapped via s_torig).
        // Superset-safe: every annotation with d<30 lies in the bucket window;
        // if the winner's exact d2 >= 900 the anchor is background and the
        // winner's identity never reaches the output.
        unsigned bestkey = 0xffffffffu;
        const ulonglong2* sp = (const ulonglong2*)s_sp;
        for (int j = 0; j < trips; j++) {      // SIMT predication = warp-max
            ulonglong2 q = sp[p0 + j];          // (-x0,-x1), (-y0,-y1)
            unsigned long long dxp, dyp, tp, d2p;
            ADD_F32X2(dxp, axx, q.x);           // (ax-x0, ax-x1)
            ADD_F32X2(dyp, ayy, q.y);
            MUL_F32X2(tp, dxp, dxp);
            FMA_F32X2(d2p, dyp, dyp, tp);       // == fmaf(dy,dy,dx*dx) per lane
            unsigned sj = (unsigned)(2 * (p0 + j));
            unsigned klo = ((unsigned)d2p & KMASK) | sj;
            unsigned khi = ((unsigned)(d2p >> 32) & KMASK) | (sj + 1u);
            bestkey = min(bestkey, min(klo, khi));
        }
        const int bestm = s_torig[bestkey & 63u];   // sorted -> original index

        // ---- epilogue: recompute EXACT values from original-order arrays ----
        const int bj = bestm >> 1, bslot = bestm & 1;
        const float bx  = -s_pair[4 * bj + bslot];
        const float by  = -s_pair[4 * bj + 2 + bslot];
        const float bal = s_al[bestm];
        const float ddx = ax - bx;
        const float ddy = ay - by;
        const float best = fmaf(ddy, ddy, ddx * ddx);
        const float dang = fabsf(aal - bal);

        // sqrt-free thresholds: dxy<20 <=> d2<400 ; dxy>=30 <=> d2>=900
        const bool positive   = (best < 400.0f) && (dang < 15.0f);
        const bool background = (best >= 900.0f) || (dang >= 22.5f);
        const bool care       = positive || background;

        if (care) {
            int label = positive ? min(max((int)s_lb[bestm], 0), NUM_C - 1) : -1;
            const float4 c4 = *(const float4*)(cls + ((size_t)b * NUM_A + a) * NUM_C);
            float cv[4] = {c4.x, c4.y, c4.z, c4.w};
            #pragma unroll
            for (int c = 0; c < NUM_C; c++) {
                float p = fminf(fmaxf(cv[c], 1e-4f), 1.0f - 1e-4f);
                bool is1 = (c == label);
                // t==1: w = 0.95*(1-p)^2, bce = -log(p)
                // t==0: w = 0.05*p^2,     bce = -log(1-p)
                float q = is1 ? (1.0f - p) : p;
                float w = (is1 ? 0.95f : 0.05f) * q * q;
                float bce = -__logf(1.0f - q);
                v0 = fmaf(w, bce, v0);
            }
        }

        if (positive) {
            const float* r3 = reg + ((size_t)b * NUM_A + a) * 3;
            float tx = bx  - ax;
            float ty = by  - ay;
            float ta = bal - aal;
            float dxr = fabsf(tx - r3[0]);
            float dyr = fabsf(ty - r3[1]);
            const float inv9 = 1.0f / 9.0f;
            float lx = (dxr <= inv9) ? (4.5f * dxr * dxr) : (dxr - 0.5f * inv9);
            float ly = (dyr <= inv9) ? (4.5f * dyr * dyr) : (dyr - 0.5f * inv9);
            v1 += lx + ly;
            v2 += fmaxf((fabsf(ta - r3[2]) - 10.0f) * 0.2f, 0.0f);
            v3 += 1.0f;
        }
    }

    // ---- block reduction: 4 quantities ----
    #pragma unroll
    for (int o = 16; o > 0; o >>= 1) {
        v0 += __shfl_down_sync(0xffffffffu, v0, o);
        v1 += __shfl_down_sync(0xffffffffu, v1, o);
        v2 += __shfl_down_sync(0xffffffffu, v2, o);
        v3 += __shfl_down_sync(0xffffffffu, v3, o);
    }
    __shared__ float red[BLOCK / 32][4];
    const int wid = tid >> 5, lid = tid & 31;
    if (lid == 0) {
        red[wid][0] = v0; red[wid][1] = v1; red[wid][2] = v2; red[wid][3] = v3;
    }
    __syncthreads();
    if (tid < 4) {
        float s = 0.0f;
        #pragma unroll
        for (int w = 0; w < BLOCK / 32; w++) s += red[w][tid];
        ((float*)&g_part[(size_t)b * GRIDX + blockIdx.x])[tid] = s;
        __threadfence();   // publish partials before the ticket increment
    }
    __syncthreads();

    // ---- last-block finalize (fused, no extra launches) ----
    __shared__ bool is_last;
    if (tid == 0) {
        unsigned v = atomicAdd(&g_count, 1u);
        is_last = (v == NBLOCKS - 1);
    }
    __syncthreads();
    if (!is_last) return;
    if (tid == 0) g_count = 0;   // reset for next graph replay

    // 8 warps: warp w reduces sample b=w over its 128 partials.
    __shared__ float s_res[NUM_B][3];
    const int w = tid >> 5, l = tid & 31;
    float4 acc = make_float4(0.f, 0.f, 0.f, 0.f);
    #pragma unroll
    for (int kk = 0; kk < GRIDX / 32; kk++) {
        float4 p = g_part[(size_t)w * GRIDX + l + 32 * kk];
        acc.x += p.x; acc.y += p.y; acc.z += p.z; acc.w += p.w;
    }
    #pragma unroll
    for (int o = 16; o > 0; o >>= 1) {
        acc.x += __shfl_down_sync(0xffffffffu, acc.x, o);
        acc.y += __shfl_down_sync(0xffffffffu, acc.y, o);
        acc.z += __shfl_down_sync(0xffffffffu, acc.z, o);
        acc.w += __shfl_down_sync(0xffffffffu, acc.w, o);
    }
    if (l == 0) {
        float denom = fmaxf(acc.w, 1.0f);
        s_res[w][0] = acc.x / denom;
        s_res[w][1] = acc.y / (2.0f * denom);
        s_res[w][2] = acc.z / denom;
    }
    __syncthreads();
    if (tid == 0) {
        float c = 0.f, x = 0.f, an = 0.f;
        #pragma unroll
        for (int bb = 0; bb < NUM_B; bb++) {
            c += s_res[bb][0]; x += s_res[bb][1]; an += s_res[bb][2];
        }
        out[0] = c  * (1.0f / NUM_B);
        out[1] = x  * (1.0f / NUM_B);
        out[2] = an * (1.0f / NUM_B);
    }
}

extern "C" void kernel_launch(void* const* d_in, const int* in_sizes, int n_in,
                              void* d_out, int out_size) {
    (void)in_sizes; (void)n_in; (void)out_size;
    const float* cls = (const float*)d_in[0];   // (B, A, C)
    const float* reg = (const float*)d_in[1];   // (B, A, 3)
    const float* anc = (const float*)d_in[2];   // (1, A, 3)
    const float* ann = (const float*)d_in[3];   // (B, M, 4)
    float* out = (float*)d_out;

    dim3 grid(GRIDX, NUM_B);
    focal_fused_kernel<<<grid, BLOCK>>>(cls, reg, anc, ann, out);
}